// round 1
// baseline (speedup 1.0000x reference)
#include <cuda_runtime.h>
#include <cuda_bf16.h>
#include <math.h>

#define B_   2
#define T_   4096
#define HID_ 2048
#define H_   16
#define D_   128
#define NC_  64      // T/CHUNK
#define CHK_ 64
#define QKVW 6144    // 3*H*D

// ---------------- scratch (static device globals; no runtime alloc) ----------------
__device__ float g_qkv[(size_t)B_ * T_ * QKVW];      // qkv projections (q,k modified in place)
__device__ float g_gate[(size_t)B_ * T_ * HID_];     // gate logits
__device__ float g_o[(size_t)B_ * T_ * HID_];        // attention output
__device__ float g_og[(size_t)B_ * T_ * HID_];       // normalized * gated

// ---------------- NT SGEMM: C[M,N] = A[M,K] * B[N,K]^T, all row-major ----------------
__global__ __launch_bounds__(256, 2)
void sgemm_nt(const float* __restrict__ A, const float* __restrict__ Bm,
              float* __restrict__ C, int M, int N, int K) {
    const int BK = 16;
    __shared__ float As[16][132];
    __shared__ float Bs[16][132];
    const int tid = threadIdx.x;
    const int bn = blockIdx.x * 128;
    const int bm = blockIdx.y * 128;
    const int tx = tid & 15;
    const int ty = tid >> 4;

    float acc[8][8];
#pragma unroll
    for (int i = 0; i < 8; i++)
#pragma unroll
        for (int j = 0; j < 8; j++) acc[i][j] = 0.f;

    for (int kb = 0; kb < K; kb += BK) {
#pragma unroll
        for (int i = 0; i < 2; i++) {
            int f = tid + i * 256;        // float4 id, 0..511
            int row = f >> 2;             // 0..127
            int k4 = (f & 3) << 2;        // 0,4,8,12
            float4 av = *(const float4*)&A[(size_t)(bm + row) * K + kb + k4];
            As[k4 + 0][row] = av.x; As[k4 + 1][row] = av.y;
            As[k4 + 2][row] = av.z; As[k4 + 3][row] = av.w;
            float4 bv = *(const float4*)&Bm[(size_t)(bn + row) * K + kb + k4];
            Bs[k4 + 0][row] = bv.x; Bs[k4 + 1][row] = bv.y;
            Bs[k4 + 2][row] = bv.z; Bs[k4 + 3][row] = bv.w;
        }
        __syncthreads();
#pragma unroll
        for (int kk = 0; kk < BK; kk++) {
            float a[8], b[8];
            *(float4*)&a[0] = *(float4*)&As[kk][ty * 8];
            *(float4*)&a[4] = *(float4*)&As[kk][ty * 8 + 4];
            *(float4*)&b[0] = *(float4*)&Bs[kk][tx * 8];
            *(float4*)&b[4] = *(float4*)&Bs[kk][tx * 8 + 4];
#pragma unroll
            for (int i = 0; i < 8; i++)
#pragma unroll
                for (int j = 0; j < 8; j++) acc[i][j] += a[i] * b[j];
        }
        __syncthreads();
    }
#pragma unroll
    for (int i = 0; i < 8; i++) {
        size_t r = (size_t)(bm + ty * 8 + i) * N + bn + tx * 8;
        *(float4*)&C[r]     = make_float4(acc[i][0], acc[i][1], acc[i][2], acc[i][3]);
        *(float4*)&C[r + 4] = make_float4(acc[i][4], acc[i][5], acc[i][6], acc[i][7]);
    }
}

// ---------------- q/k rmsnorm + RoPE (+ q * D^-0.5), in place on g_qkv ----------------
__global__ __launch_bounds__(256)
void prep_qk(float* __restrict__ qkv, const float* __restrict__ qw,
             const float* __restrict__ kw, const int* __restrict__ pos_ids) {
    const int bt = blockIdx.x;                 // 0..B*T-1
    const int lane = threadIdx.x & 31;
    const int warp = threadIdx.x >> 5;         // 0..7
    const float pos = (float)pos_ids[bt];
    // inv_freq[lane] = theta^(-lane/32)
    const float invf = expf(-(float)lane * (logf(10000.0f) / 32.0f));
    const float fr = pos * invf;
    const float cs = cosf(fr), sn = sinf(fr);

    for (int r = warp; r < 32; r += 8) {
        const int hh = r >> 1;
        const int isK = r & 1;
        float* row = qkv + (size_t)bt * QKVW + isK * (H_ * D_) + hh * D_;
        const float* w = isK ? kw : qw;
        float v0 = row[lane], v1 = row[lane + 32], v2 = row[lane + 64], v3 = row[lane + 96];
        float ss = v0 * v0 + v1 * v1 + v2 * v2 + v3 * v3;
#pragma unroll
        for (int o = 16; o; o >>= 1) ss += __shfl_xor_sync(0xFFFFFFFFu, ss, o);
        const float rs = rsqrtf(ss * (1.f / 128.f) + 1e-6f);
        v0 = v0 * rs * w[lane];      v1 = v1 * rs * w[lane + 32];
        v2 = v2 * rs * w[lane + 64]; v3 = v3 * rs * w[lane + 96];
        // RoPE on dims [0,64): d=lane pairs with d=lane+32
        float nv0 = v0 * cs - v1 * sn;
        float nv1 = v1 * cs + v0 * sn;
        v0 = nv0; v1 = nv1;
        if (!isK) {
            const float sc = 0.08838834764831845f;   // 128^-0.5
            v0 *= sc; v1 *= sc; v2 *= sc; v3 *= sc;
        }
        row[lane] = v0; row[lane + 32] = v1; row[lane + 64] = v2; row[lane + 96] = v3;
    }
}

// ---------------- chunked GLA ----------------
// grid (4, H, B): each block owns a 32-wide slice of the value/state dim,
// runs 64 chunks sequentially with state S[128x32] in smem.
#define GLA_SMEM_FLOATS (64*132 + 64*132 + 64*36 + 128*36 + 64*68 + 80)

__global__ __launch_bounds__(256)
void gla_kernel(const float* __restrict__ qkv, float* __restrict__ o_out) {
    extern __shared__ float sm[];
    float* sQ   = sm;                    // [64][132]
    float* sK   = sQ + 64 * 132;         // [64][132]
    float* sV   = sK + 64 * 132;         // [64][36]
    float* sS   = sV + 64 * 36;          // [128][36]
    float* sAtt = sS + 128 * 36;         // [64][68]
    float* expg = sAtt + 64 * 68;        // [80]

    const int tid = threadIdx.x;
    const int gs = blockIdx.x;           // value-dim slice 0..3
    const int h  = blockIdx.y;
    const int b  = blockIdx.z;

    float g;
    {
        const double scale = 1.0 - 11.0 / 31.0 + 1e-5;
        const double sl = pow(2.0, -0.5 * (double)(h + 1));
        g = (float)(-sl * scale);
    }
    if (tid <= 64) expg[tid] = expf(g * (float)tid);
    for (int i = tid; i < 128 * 36; i += 256) sS[i] = 0.f;
    __syncthreads();
    const float chdec = expg[64];

    const float* qb = qkv + (size_t)b * T_ * QKVW + h * D_;
    const int dvb = gs * 32;

    for (int ck = 0; ck < NC_; ck++) {
        const float* crow = qb + (size_t)ck * CHK_ * QKVW;
        // load q,k full [64x128], v slice [64x32]
        for (int f = tid; f < 64 * 32; f += 256) {
            int r = f >> 5;
            int d4 = (f & 31) << 2;
            float4 qv = *(const float4*)(crow + (size_t)r * QKVW + d4);
            *(float4*)&sQ[r * 132 + d4] = qv;
            float4 kv = *(const float4*)(crow + (size_t)r * QKVW + 2048 + d4);
            *(float4*)&sK[r * 132 + d4] = kv;
        }
        for (int f = tid; f < 64 * 8; f += 256) {
            int r = f >> 3;
            int d4 = (f & 7) << 2;
            float4 vv = *(const float4*)(crow + (size_t)r * QKVW + 4096 + dvb + d4);
            *(float4*)&sV[r * 36 + d4] = vv;
        }
        __syncthreads();

        // att[c][e] = (q[c]·k[e]) * mask
        {
            const int c0 = (tid >> 4) << 2;
            const int e0 = (tid & 15) << 2;
            float acc[4][4];
#pragma unroll
            for (int i = 0; i < 4; i++)
#pragma unroll
                for (int j = 0; j < 4; j++) acc[i][j] = 0.f;
#pragma unroll 8
            for (int d4 = 0; d4 < 128; d4 += 4) {
                float4 qv[4], kv[4];
#pragma unroll
                for (int i = 0; i < 4; i++) qv[i] = *(float4*)&sQ[(c0 + i) * 132 + d4];
#pragma unroll
                for (int j = 0; j < 4; j++) kv[j] = *(float4*)&sK[(e0 + j) * 132 + d4];
#pragma unroll
                for (int i = 0; i < 4; i++)
#pragma unroll
                    for (int j = 0; j < 4; j++)
                        acc[i][j] += qv[i].x * kv[j].x + qv[i].y * kv[j].y +
                                     qv[i].z * kv[j].z + qv[i].w * kv[j].w;
            }
#pragma unroll
            for (int i = 0; i < 4; i++)
#pragma unroll
                for (int j = 0; j < 4; j++) {
                    int c = c0 + i, e = e0 + j;
                    sAtt[c * 68 + e] = (c >= e) ? acc[i][j] * expg[c - e] : 0.f;
                }
        }
        __syncthreads();

        // o[c][dv] = intra + qdec[c] * (q[c] @ S[:,dv])
        {
            const int c0 = (tid >> 3) << 1;
            const int dv0 = (tid & 7) << 2;
            float ai[2][4], ar[2][4];
#pragma unroll
            for (int i = 0; i < 2; i++)
#pragma unroll
                for (int j = 0; j < 4; j++) { ai[i][j] = 0.f; ar[i][j] = 0.f; }
#pragma unroll 4
            for (int e = 0; e < 64; e++) {
                float a0 = sAtt[c0 * 68 + e], a1 = sAtt[(c0 + 1) * 68 + e];
                float4 vv = *(float4*)&sV[e * 36 + dv0];
                ai[0][0] += a0 * vv.x; ai[0][1] += a0 * vv.y; ai[0][2] += a0 * vv.z; ai[0][3] += a0 * vv.w;
                ai[1][0] += a1 * vv.x; ai[1][1] += a1 * vv.y; ai[1][2] += a1 * vv.z; ai[1][3] += a1 * vv.w;
            }
#pragma unroll 4
            for (int d = 0; d < 128; d++) {
                float q0 = sQ[c0 * 132 + d], q1 = sQ[(c0 + 1) * 132 + d];
                float4 sv = *(float4*)&sS[d * 36 + dv0];
                ar[0][0] += q0 * sv.x; ar[0][1] += q0 * sv.y; ar[0][2] += q0 * sv.z; ar[0][3] += q0 * sv.w;
                ar[1][0] += q1 * sv.x; ar[1][1] += q1 * sv.y; ar[1][2] += q1 * sv.z; ar[1][3] += q1 * sv.w;
            }
            const float qd0 = expg[c0 + 1], qd1 = expg[c0 + 2];
            size_t ob = ((size_t)b * T_ + (size_t)ck * CHK_ + c0) * HID_ + h * D_ + dvb + dv0;
            *(float4*)(o_out + ob) = make_float4(
                ai[0][0] + qd0 * ar[0][0], ai[0][1] + qd0 * ar[0][1],
                ai[0][2] + qd0 * ar[0][2], ai[0][3] + qd0 * ar[0][3]);
            *(float4*)(o_out + ob + HID_) = make_float4(
                ai[1][0] + qd1 * ar[1][0], ai[1][1] + qd1 * ar[1][1],
                ai[1][2] + qd1 * ar[1][2], ai[1][3] + qd1 * ar[1][3]);
        }
        __syncthreads();

        // S[d][dv] = chdec*S + sum_c (k[c][d]*kdec[c]) * v[c][dv]
        {
            const int d0 = (tid >> 3) << 2;
            const int dv0 = (tid & 7) << 2;
            float acc[4][4];
#pragma unroll
            for (int i = 0; i < 4; i++)
#pragma unroll
                for (int j = 0; j < 4; j++) acc[i][j] = 0.f;
#pragma unroll 4
            for (int c = 0; c < 64; c++) {
                const float kd = expg[63 - c];
                float4 kv = *(float4*)&sK[c * 132 + d0];
                kv.x *= kd; kv.y *= kd; kv.z *= kd; kv.w *= kd;
                float4 vv = *(float4*)&sV[c * 36 + dv0];
                acc[0][0] += kv.x * vv.x; acc[0][1] += kv.x * vv.y; acc[0][2] += kv.x * vv.z; acc[0][3] += kv.x * vv.w;
                acc[1][0] += kv.y * vv.x; acc[1][1] += kv.y * vv.y; acc[1][2] += kv.y * vv.z; acc[1][3] += kv.y * vv.w;
                acc[2][0] += kv.z * vv.x; acc[2][1] += kv.z * vv.y; acc[2][2] += kv.z * vv.z; acc[2][3] += kv.z * vv.w;
                acc[3][0] += kv.w * vv.x; acc[3][1] += kv.w * vv.y; acc[3][2] += kv.w * vv.z; acc[3][3] += kv.w * vv.w;
            }
#pragma unroll
            for (int i = 0; i < 4; i++) {
                float4 s = *(float4*)&sS[(d0 + i) * 36 + dv0];
                s.x = s.x * chdec + acc[i][0];
                s.y = s.y * chdec + acc[i][1];
                s.z = s.z * chdec + acc[i][2];
                s.w = s.w * chdec + acc[i][3];
                *(float4*)&sS[(d0 + i) * 36 + dv0] = s;
            }
        }
        __syncthreads();
    }
}

// ---------------- group rmsnorm * sigmoid(gate) ----------------
__global__ __launch_bounds__(256)
void epilogue_k(const float* __restrict__ o_in, const float* __restrict__ gate,
                const float* __restrict__ gw, float* __restrict__ og) {
    const int bt = blockIdx.x;
    const int lane = threadIdx.x & 31;
    const int warp = threadIdx.x >> 5;
    for (int hh = warp; hh < H_; hh += 8) {
        const size_t base = (size_t)bt * HID_ + hh * D_;
        const float* row = o_in + base;
        float v0 = row[lane], v1 = row[lane + 32], v2 = row[lane + 64], v3 = row[lane + 96];
        float ss = v0 * v0 + v1 * v1 + v2 * v2 + v3 * v3;
#pragma unroll
        for (int o = 16; o; o >>= 1) ss += __shfl_xor_sync(0xFFFFFFFFu, ss, o);
        const float rs = rsqrtf(ss * (1.f / 128.f) + 1e-6f);
        const float* gr = gate + base;
        float* out = og + base;
#pragma unroll
        for (int i = 0; i < 4; i++) {
            const int d = lane + 32 * i;
            float v = (i == 0) ? v0 : (i == 1) ? v1 : (i == 2) ? v2 : v3;
            float sg = 1.f / (1.f + expf(-gr[d]));
            out[d] = v * rs * gw[hh * D_ + d] * sg;
        }
    }
}

// ---------------- launch ----------------
extern "C" void kernel_launch(void* const* d_in, const int* in_sizes, int n_in,
                              void* d_out, int out_size) {
    const float* hidden   = (const float*)d_in[0];
    const float* w_qkv    = (const float*)d_in[1];
    const float* q_ln_w   = (const float*)d_in[2];
    const float* k_ln_w   = (const float*)d_in[3];
    const float* g_norm_w = (const float*)d_in[4];
    const float* w_g_proj = (const float*)d_in[5];
    const float* w_dense  = (const float*)d_in[6];
    const int*   pos_ids  = (const int*)d_in[7];
    float* out = (float*)d_out;

    float *qkv_p, *gate_p, *o_p, *og_p;
    cudaGetSymbolAddress((void**)&qkv_p, g_qkv);
    cudaGetSymbolAddress((void**)&gate_p, g_gate);
    cudaGetSymbolAddress((void**)&o_p, g_o);
    cudaGetSymbolAddress((void**)&og_p, g_og);

    const int M = B_ * T_;
    cudaFuncSetAttribute(gla_kernel, cudaFuncAttributeMaxDynamicSharedMemorySize,
                         GLA_SMEM_FLOATS * (int)sizeof(float));

    // 1) qkv projection
    sgemm_nt<<<dim3(QKVW / 128, M / 128), 256>>>(hidden, w_qkv, qkv_p, M, QKVW, HID_);
    // 2) gate projection
    sgemm_nt<<<dim3(HID_ / 128, M / 128), 256>>>(hidden, w_g_proj, gate_p, M, HID_, HID_);
    // 3) rmsnorm + rope on q,k
    prep_qk<<<M, 256>>>(qkv_p, q_ln_w, k_ln_w, pos_ids);
    // 4) chunked gated linear attention
    gla_kernel<<<dim3(4, H_, B_), 256, GLA_SMEM_FLOATS * sizeof(float)>>>(qkv_p, o_p);
    // 5) group rmsnorm * sigmoid gate
    epilogue_k<<<M, 256>>>(o_p, gate_p, g_norm_w, og_p);
    // 6) dense output projection
    sgemm_nt<<<dim3(HID_ / 128, M / 128), 256>>>(og_p, w_dense, out, M, HID_, HID_);
}

// round 4
// speedup vs baseline: 2.5735x; 2.5735x over previous
#include <cuda_runtime.h>
#include <cuda_bf16.h>
#include <cstdint>
#include <math.h>

#define B_   2
#define T_   4096
#define HID_ 2048
#define H_   16
#define D_   128
#define NC_  64      // T/CHUNK
#define CHK_ 64
#define QKVW 6144    // 3*H*D

// ---------------- scratch (static device globals; no runtime alloc) ----------------
__device__ float g_qkv[(size_t)B_ * T_ * QKVW];
__device__ float g_gate[(size_t)B_ * T_ * HID_];
__device__ float g_o[(size_t)B_ * T_ * HID_];
__device__ float g_og[(size_t)B_ * T_ * HID_];
__device__ float g_hid[(size_t)B_ * T_ * HID_];      // tf32-rounded hidden
__device__ float g_wqkv[(size_t)QKVW * HID_];        // tf32-rounded weights
__device__ float g_wg[(size_t)HID_ * HID_];
__device__ float g_wd[(size_t)HID_ * HID_];

// ================= helpers =================
__device__ __forceinline__ uint32_t smem_u32(const void* p) {
    uint32_t a;
    asm("{ .reg .u64 t; cvta.to.shared.u64 t, %1; cvt.u32.u64 %0, t; }" : "=r"(a) : "l"(p));
    return a;
}
#define CP_ASYNC16(dst, src) \
    asm volatile("cp.async.cg.shared.global [%0], [%1], 16;" \
                 :: "r"(dst), "l"(__cvta_generic_to_global(src)))
#define CP_COMMIT() asm volatile("cp.async.commit_group;" ::: "memory")
#define CP_WAIT1()  asm volatile("cp.async.wait_group 1;" ::: "memory")

__device__ __forceinline__ void mma_tf32(float* d, const uint32_t* a, const uint32_t* b) {
    asm volatile(
        "mma.sync.aligned.m16n8k8.row.col.f32.tf32.tf32.f32 "
        "{%0,%1,%2,%3}, {%4,%5,%6,%7}, {%8,%9}, {%0,%1,%2,%3};"
        : "+f"(d[0]), "+f"(d[1]), "+f"(d[2]), "+f"(d[3])
        : "r"(a[0]), "r"(a[1]), "r"(a[2]), "r"(a[3]), "r"(b[0]), "r"(b[1]));
}

// ---------------- tf32 round-to-nearest pre-pass (bits + 0x1000) ----------------
__global__ __launch_bounds__(256)
void round_tf32_k(const uint4* __restrict__ in, uint4* __restrict__ out, int n4) {
    int i = blockIdx.x * blockDim.x + threadIdx.x;
    if (i < n4) {
        uint4 v = in[i];
        v.x += 0x1000u; v.y += 0x1000u; v.z += 0x1000u; v.w += 0x1000u;
        out[i] = v;
    }
}

// ================= tf32 mma.sync NT GEMM: C[M,N] = A[M,K] * B[N,K]^T =================
// Block tile 128x128, BK=32, 8 warps (2x4), warp tile 64x32 of m16n8k8.
// Smem: per stage A[128][36] + B[128][36] floats (padded rows, 16B-granular).
#define GPAD  36
#define GSTGF (256 * GPAD)                 // floats per stage (A+B)
#define GSMEM (2 * GSTGF * 4)              // 73728 bytes

__global__ __launch_bounds__(256, 2)
void gemm_mma(const float* __restrict__ A, const float* __restrict__ Bm,
              float* __restrict__ C, int M, int N, int K) {
    extern __shared__ float gsm[];
    const uint32_t sb = smem_u32(gsm);
    const int tid = threadIdx.x;
    const int lane = tid & 31, wid = tid >> 5;
    const int g = lane >> 2, c = lane & 3;
    const int bm = blockIdx.y * 128, bn = blockIdx.x * 128;
    const int wm = (wid >> 2) * 64, wn = (wid & 3) * 32;
    const int KIT = K >> 5;

    // cp.async stage loader: stage s <- k-chunk kt
    auto load_stage = [&](int s, int kt) {
        const uint32_t ab = sb + (uint32_t)s * (GSTGF * 4);
        const uint32_t bb = ab + 128 * GPAD * 4;
        const size_t kofs = (size_t)kt * 32;
#pragma unroll
        for (int i = 0; i < 4; i++) {
            int id = tid + i * 256;          // 0..1023
            int row = id >> 3, c8 = id & 7;  // 16B chunk in row
            CP_ASYNC16(ab + (uint32_t)(row * (GPAD * 4) + c8 * 16),
                       A + (size_t)(bm + row) * K + kofs + c8 * 4);
        }
#pragma unroll
        for (int i = 0; i < 4; i++) {
            int id = tid + i * 256;
            int row = id >> 3, c8 = id & 7;
            CP_ASYNC16(bb + (uint32_t)(row * (GPAD * 4) + c8 * 16),
                       Bm + (size_t)(bn + row) * K + kofs + c8 * 4);
        }
    };

    float d[4][4][4];
#pragma unroll
    for (int mt = 0; mt < 4; mt++)
#pragma unroll
        for (int nt = 0; nt < 4; nt++)
#pragma unroll
            for (int i = 0; i < 4; i++) d[mt][nt][i] = 0.f;

    load_stage(0, 0);
    CP_COMMIT();

    for (int it = 0; it < KIT; it++) {
        if (it + 1 < KIT) load_stage((it + 1) & 1, it + 1);
        CP_COMMIT();
        CP_WAIT1();
        __syncthreads();

        const float* As = gsm + (it & 1) * GSTGF;
        const float* Bs = As + 128 * GPAD;
#pragma unroll
        for (int k0 = 0; k0 < 4; k0++) {
            uint32_t a[4][4];
#pragma unroll
            for (int mt = 0; mt < 4; mt++) {
                const float* p = As + (wm + mt * 16 + g) * GPAD + k0 * 8 + c;
                a[mt][0] = __float_as_uint(p[0]);
                a[mt][1] = __float_as_uint(p[8 * GPAD]);
                a[mt][2] = __float_as_uint(p[4]);
                a[mt][3] = __float_as_uint(p[8 * GPAD + 4]);
            }
            uint32_t b[4][2];
#pragma unroll
            for (int nt = 0; nt < 4; nt++) {
                const float* p = Bs + (wn + nt * 8 + g) * GPAD + k0 * 8 + c;
                b[nt][0] = __float_as_uint(p[0]);
                b[nt][1] = __float_as_uint(p[4]);
            }
#pragma unroll
            for (int mt = 0; mt < 4; mt++)
#pragma unroll
                for (int nt = 0; nt < 4; nt++)
                    mma_tf32(d[mt][nt], a[mt], b[nt]);
        }
        __syncthreads();
    }

    // epilogue: d[mt][nt]: rows (wm+mt*16+g, +8), cols (wn+nt*8+2c, +1)
#pragma unroll
    for (int mt = 0; mt < 4; mt++) {
        const int r0 = bm + wm + mt * 16 + g;
#pragma unroll
        for (int nt = 0; nt < 4; nt++) {
            const int c0 = bn + wn + nt * 8 + 2 * c;
            *(float2*)&C[(size_t)r0 * N + c0]       = make_float2(d[mt][nt][0], d[mt][nt][1]);
            *(float2*)&C[(size_t)(r0 + 8) * N + c0] = make_float2(d[mt][nt][2], d[mt][nt][3]);
        }
    }
}

// ---------------- q/k rmsnorm + RoPE (+ q * D^-0.5), in place on g_qkv ----------------
__global__ __launch_bounds__(256)
void prep_qk(float* __restrict__ qkv, const float* __restrict__ qw,
             const float* __restrict__ kw, const int* __restrict__ pos_ids) {
    const int bt = blockIdx.x;
    const int lane = threadIdx.x & 31;
    const int warp = threadIdx.x >> 5;
    const float pos = (float)pos_ids[bt];
    const float invf = expf(-(float)lane * (logf(10000.0f) / 32.0f));
    const float fr = pos * invf;
    const float cs = cosf(fr), sn = sinf(fr);

    for (int r = warp; r < 32; r += 8) {
        const int hh = r >> 1;
        const int isK = r & 1;
        float* row = qkv + (size_t)bt * QKVW + isK * (H_ * D_) + hh * D_;
        const float* w = isK ? kw : qw;
        float v0 = row[lane], v1 = row[lane + 32], v2 = row[lane + 64], v3 = row[lane + 96];
        float ss = v0 * v0 + v1 * v1 + v2 * v2 + v3 * v3;
#pragma unroll
        for (int o = 16; o; o >>= 1) ss += __shfl_xor_sync(0xFFFFFFFFu, ss, o);
        const float rs = rsqrtf(ss * (1.f / 128.f) + 1e-6f);
        v0 = v0 * rs * w[lane];      v1 = v1 * rs * w[lane + 32];
        v2 = v2 * rs * w[lane + 64]; v3 = v3 * rs * w[lane + 96];
        float nv0 = v0 * cs - v1 * sn;
        float nv1 = v1 * cs + v0 * sn;
        v0 = nv0; v1 = nv1;
        if (!isK) {
            const float sc = 0.08838834764831845f;
            v0 *= sc; v1 *= sc; v2 *= sc; v3 *= sc;
        }
        row[lane] = v0; row[lane + 32] = v1; row[lane + 64] = v2; row[lane + 96] = v3;
    }
}

// ---------------- chunked GLA ----------------
#define GLA_SMEM_FLOATS (64*132 + 64*132 + 64*36 + 128*36 + 64*68 + 80)

__global__ __launch_bounds__(256)
void gla_kernel(const float* __restrict__ qkv, float* __restrict__ o_out) {
    extern __shared__ float sm[];
    float* sQ   = sm;
    float* sK   = sQ + 64 * 132;
    float* sV   = sK + 64 * 132;
    float* sS   = sV + 64 * 36;
    float* sAtt = sS + 128 * 36;
    float* expg = sAtt + 64 * 68;

    const int tid = threadIdx.x;
    const int gs = blockIdx.x;
    const int h  = blockIdx.y;
    const int b  = blockIdx.z;

    float g;
    {
        const double scale = 1.0 - 11.0 / 31.0 + 1e-5;
        const double sl = pow(2.0, -0.5 * (double)(h + 1));
        g = (float)(-sl * scale);
    }
    if (tid <= 64) expg[tid] = expf(g * (float)tid);
    for (int i = tid; i < 128 * 36; i += 256) sS[i] = 0.f;
    __syncthreads();
    const float chdec = expg[64];

    const float* qb = qkv + (size_t)b * T_ * QKVW + h * D_;
    const int dvb = gs * 32;

    for (int ck = 0; ck < NC_; ck++) {
        const float* crow = qb + (size_t)ck * CHK_ * QKVW;
        for (int f = tid; f < 64 * 32; f += 256) {
            int r = f >> 5;
            int d4 = (f & 31) << 2;
            float4 qv = *(const float4*)(crow + (size_t)r * QKVW + d4);
            *(float4*)&sQ[r * 132 + d4] = qv;
            float4 kv = *(const float4*)(crow + (size_t)r * QKVW + 2048 + d4);
            *(float4*)&sK[r * 132 + d4] = kv;
        }
        for (int f = tid; f < 64 * 8; f += 256) {
            int r = f >> 3;
            int d4 = (f & 7) << 2;
            float4 vv = *(const float4*)(crow + (size_t)r * QKVW + 4096 + dvb + d4);
            *(float4*)&sV[r * 36 + d4] = vv;
        }
        __syncthreads();

        {
            const int c0 = (tid >> 4) << 2;
            const int e0 = (tid & 15) << 2;
            float acc[4][4];
#pragma unroll
            for (int i = 0; i < 4; i++)
#pragma unroll
                for (int j = 0; j < 4; j++) acc[i][j] = 0.f;
#pragma unroll 8
            for (int d4 = 0; d4 < 128; d4 += 4) {
                float4 qv[4], kv[4];
#pragma unroll
                for (int i = 0; i < 4; i++) qv[i] = *(float4*)&sQ[(c0 + i) * 132 + d4];
#pragma unroll
                for (int j = 0; j < 4; j++) kv[j] = *(float4*)&sK[(e0 + j) * 132 + d4];
#pragma unroll
                for (int i = 0; i < 4; i++)
#pragma unroll
                    for (int j = 0; j < 4; j++)
                        acc[i][j] += qv[i].x * kv[j].x + qv[i].y * kv[j].y +
                                     qv[i].z * kv[j].z + qv[i].w * kv[j].w;
            }
#pragma unroll
            for (int i = 0; i < 4; i++)
#pragma unroll
                for (int j = 0; j < 4; j++) {
                    int cc = c0 + i, e = e0 + j;
                    sAtt[cc * 68 + e] = (cc >= e) ? acc[i][j] * expg[cc - e] : 0.f;
                }
        }
        __syncthreads();

        {
            const int c0 = (tid >> 3) << 1;
            const int dv0 = (tid & 7) << 2;
            float ai[2][4], ar[2][4];
#pragma unroll
            for (int i = 0; i < 2; i++)
#pragma unroll
                for (int j = 0; j < 4; j++) { ai[i][j] = 0.f; ar[i][j] = 0.f; }
#pragma unroll 4
            for (int e = 0; e < 64; e++) {
                float a0 = sAtt[c0 * 68 + e], a1 = sAtt[(c0 + 1) * 68 + e];
                float4 vv = *(float4*)&sV[e * 36 + dv0];
                ai[0][0] += a0 * vv.x; ai[0][1] += a0 * vv.y; ai[0][2] += a0 * vv.z; ai[0][3] += a0 * vv.w;
                ai[1][0] += a1 * vv.x; ai[1][1] += a1 * vv.y; ai[1][2] += a1 * vv.z; ai[1][3] += a1 * vv.w;
            }
#pragma unroll 4
            for (int dd = 0; dd < 128; dd++) {
                float q0 = sQ[c0 * 132 + dd], q1 = sQ[(c0 + 1) * 132 + dd];
                float4 sv = *(float4*)&sS[dd * 36 + dv0];
                ar[0][0] += q0 * sv.x; ar[0][1] += q0 * sv.y; ar[0][2] += q0 * sv.z; ar[0][3] += q0 * sv.w;
                ar[1][0] += q1 * sv.x; ar[1][1] += q1 * sv.y; ar[1][2] += q1 * sv.z; ar[1][3] += q1 * sv.w;
            }
            const float qd0 = expg[c0 + 1], qd1 = expg[c0 + 2];
            size_t ob = ((size_t)b * T_ + (size_t)ck * CHK_ + c0) * HID_ + h * D_ + dvb + dv0;
            *(float4*)(o_out + ob) = make_float4(
                ai[0][0] + qd0 * ar[0][0], ai[0][1] + qd0 * ar[0][1],
                ai[0][2] + qd0 * ar[0][2], ai[0][3] + qd0 * ar[0][3]);
            *(float4*)(o_out + ob + HID_) = make_float4(
                ai[1][0] + qd1 * ar[1][0], ai[1][1] + qd1 * ar[1][1],
                ai[1][2] + qd1 * ar[1][2], ai[1][3] + qd1 * ar[1][3]);
        }
        __syncthreads();

        {
            const int d0 = (tid >> 3) << 2;
            const int dv0 = (tid & 7) << 2;
            float acc[4][4];
#pragma unroll
            for (int i = 0; i < 4; i++)
#pragma unroll
                for (int j = 0; j < 4; j++) acc[i][j] = 0.f;
#pragma unroll 4
            for (int cc = 0; cc < 64; cc++) {
                const float kd = expg[63 - cc];
                float4 kv = *(float4*)&sK[cc * 132 + d0];
                kv.x *= kd; kv.y *= kd; kv.z *= kd; kv.w *= kd;
                float4 vv = *(float4*)&sV[cc * 36 + dv0];
                acc[0][0] += kv.x * vv.x; acc[0][1] += kv.x * vv.y; acc[0][2] += kv.x * vv.z; acc[0][3] += kv.x * vv.w;
                acc[1][0] += kv.y * vv.x; acc[1][1] += kv.y * vv.y; acc[1][2] += kv.y * vv.z; acc[1][3] += kv.y * vv.w;
                acc[2][0] += kv.z * vv.x; acc[2][1] += kv.z * vv.y; acc[2][2] += kv.z * vv.z; acc[2][3] += kv.z * vv.w;
                acc[3][0] += kv.w * vv.x; acc[3][1] += kv.w * vv.y; acc[3][2] += kv.w * vv.z; acc[3][3] += kv.w * vv.w;
            }
#pragma unroll
            for (int i = 0; i < 4; i++) {
                float4 s = *(float4*)&sS[(d0 + i) * 36 + dv0];
                s.x = s.x * chdec + acc[i][0];
                s.y = s.y * chdec + acc[i][1];
                s.z = s.z * chdec + acc[i][2];
                s.w = s.w * chdec + acc[i][3];
                *(float4*)&sS[(d0 + i) * 36 + dv0] = s;
            }
        }
        __syncthreads();
    }
}

// ---------------- group rmsnorm * sigmoid(gate), output tf32-rounded ----------------
__global__ __launch_bounds__(256)
void epilogue_k(const float* __restrict__ o_in, const float* __restrict__ gate,
                const float* __restrict__ gw, float* __restrict__ og) {
    const int bt = blockIdx.x;
    const int lane = threadIdx.x & 31;
    const int warp = threadIdx.x >> 5;
    for (int hh = warp; hh < H_; hh += 8) {
        const size_t base = (size_t)bt * HID_ + hh * D_;
        const float* row = o_in + base;
        float v0 = row[lane], v1 = row[lane + 32], v2 = row[lane + 64], v3 = row[lane + 96];
        float ss = v0 * v0 + v1 * v1 + v2 * v2 + v3 * v3;
#pragma unroll
        for (int o = 16; o; o >>= 1) ss += __shfl_xor_sync(0xFFFFFFFFu, ss, o);
        const float rs = rsqrtf(ss * (1.f / 128.f) + 1e-6f);
        const float* gr = gate + base;
        float* out = og + base;
#pragma unroll
        for (int i = 0; i < 4; i++) {
            const int d = lane + 32 * i;
            float v = (i == 0) ? v0 : (i == 1) ? v1 : (i == 2) ? v2 : v3;
            float sg = 1.f / (1.f + expf(-gr[d]));
            float val = v * rs * gw[hh * D_ + d] * sg;
            out[d] = __uint_as_float(__float_as_uint(val) + 0x1000u);  // tf32 RN for GEMM3
        }
    }
}

// ---------------- launch ----------------
extern "C" void kernel_launch(void* const* d_in, const int* in_sizes, int n_in,
                              void* d_out, int out_size) {
    const float* hidden   = (const float*)d_in[0];
    const float* w_qkv    = (const float*)d_in[1];
    const float* q_ln_w   = (const float*)d_in[2];
    const float* k_ln_w   = (const float*)d_in[3];
    const float* g_norm_w = (const float*)d_in[4];
    const float* w_g_proj = (const float*)d_in[5];
    const float* w_dense  = (const float*)d_in[6];
    const int*   pos_ids  = (const int*)d_in[7];
    float* out = (float*)d_out;

    float *qkv_p, *gate_p, *o_p, *og_p, *hid_p, *wqkv_p, *wg_p, *wd_p;
    cudaGetSymbolAddress((void**)&qkv_p, g_qkv);
    cudaGetSymbolAddress((void**)&gate_p, g_gate);
    cudaGetSymbolAddress((void**)&o_p, g_o);
    cudaGetSymbolAddress((void**)&og_p, g_og);
    cudaGetSymbolAddress((void**)&hid_p, g_hid);
    cudaGetSymbolAddress((void**)&wqkv_p, g_wqkv);
    cudaGetSymbolAddress((void**)&wg_p, g_wg);
    cudaGetSymbolAddress((void**)&wd_p, g_wd);

    const int M = B_ * T_;
    cudaFuncSetAttribute(gla_kernel, cudaFuncAttributeMaxDynamicSharedMemorySize,
                         GLA_SMEM_FLOATS * (int)sizeof(float));
    cudaFuncSetAttribute(gemm_mma, cudaFuncAttributeMaxDynamicSharedMemorySize, GSMEM);

    // 0) tf32 round-to-nearest pre-pass on GEMM inputs
    {
        int n4;
        n4 = (M * HID_) / 4;
        round_tf32_k<<<(n4 + 255) / 256, 256>>>((const uint4*)hidden, (uint4*)hid_p, n4);
        n4 = (QKVW * HID_) / 4;
        round_tf32_k<<<(n4 + 255) / 256, 256>>>((const uint4*)w_qkv, (uint4*)wqkv_p, n4);
        n4 = (HID_ * HID_) / 4;
        round_tf32_k<<<(n4 + 255) / 256, 256>>>((const uint4*)w_g_proj, (uint4*)wg_p, n4);
        round_tf32_k<<<(n4 + 255) / 256, 256>>>((const uint4*)w_dense, (uint4*)wd_p, n4);
    }

    // 1) qkv projection (tf32 mma.sync tensor cores)
    gemm_mma<<<dim3(QKVW / 128, M / 128), 256, GSMEM>>>(hid_p, wqkv_p, qkv_p, M, QKVW, HID_);
    // 2) gate projection
    gemm_mma<<<dim3(HID_ / 128, M / 128), 256, GSMEM>>>(hid_p, wg_p, gate_p, M, HID_, HID_);
    // 3) rmsnorm + rope on q,k
    prep_qk<<<M, 256>>>(qkv_p, q_ln_w, k_ln_w, pos_ids);
    // 4) chunked gated linear attention
    gla_kernel<<<dim3(4, H_, B_), 256, GLA_SMEM_FLOATS * sizeof(float)>>>(qkv_p, o_p);
    // 5) group rmsnorm * sigmoid gate (emits tf32-rounded og)
    epilogue_k<<<M, 256>>>(o_p, gate_p, g_norm_w, og_p);
    // 6) dense output projection
    gemm_mma<<<dim3(HID_ / 128, M / 128), 256, GSMEM>>>(og_p, wd_p, out, M, HID_, HID_);
}

// round 6
// speedup vs baseline: 3.4338x; 1.3343x over previous
#include <cuda_runtime.h>
#include <cuda_bf16.h>
#include <cstdint>
#include <math.h>

#define B_   2
#define T_   4096
#define HID_ 2048
#define H_   16
#define D_   128
#define NC_  64      // T/CHUNK
#define CHK_ 64
#define QKVW 6144    // 3*H*D

// ---------------- scratch (static device globals; no runtime alloc) ----------------
__device__ float g_qkv[(size_t)B_ * T_ * QKVW];
__device__ float g_gate[(size_t)B_ * T_ * HID_];
__device__ float g_o[(size_t)B_ * T_ * HID_];
__device__ float g_og[(size_t)B_ * T_ * HID_];

// ================= helpers =================
__device__ __forceinline__ uint32_t smem_u32(const void* p) {
    uint32_t a;
    asm("{ .reg .u64 t; cvta.to.shared.u64 t, %1; cvt.u32.u64 %0, t; }" : "=r"(a) : "l"(p));
    return a;
}
#define CP_ASYNC16(dst, src) \
    asm volatile("cp.async.cg.shared.global [%0], [%1], 16;" \
                 :: "r"(dst), "l"(__cvta_generic_to_global(src)))
#define CP_COMMIT() asm volatile("cp.async.commit_group;" ::: "memory")
#define CP_WAIT1()  asm volatile("cp.async.wait_group 1;" ::: "memory")

__device__ __forceinline__ void mma_tf32(float* d, const uint32_t* a, const uint32_t* b) {
    asm volatile(
        "mma.sync.aligned.m16n8k8.row.col.f32.tf32.tf32.f32 "
        "{%0,%1,%2,%3}, {%4,%5,%6,%7}, {%8,%9}, {%0,%1,%2,%3};"
        : "+f"(d[0]), "+f"(d[1]), "+f"(d[2]), "+f"(d[3])
        : "r"(a[0]), "r"(a[1]), "r"(a[2]), "r"(a[3]), "r"(b[0]), "r"(b[1]));
}

// tf32 round-to-nearest on fp32 bit pattern
__device__ __forceinline__ float rtf(float x) {
    return __uint_as_float(__float_as_uint(x) + 0x1000u);
}
__device__ __forceinline__ uint32_t rtu(float x) {
    return __float_as_uint(x) + 0x1000u;
}

// ================= tf32 mma.sync NT GEMM: C[M,N] = A[M,K] * B[N,K]^T =================
// Block tile 128x128, BK=32, 8 warps (2x4), warp tile 64x32 of m16n8k8.
// tf32 RN rounding fused into fragment loads.
#define GPAD  36
#define GSTGF (256 * GPAD)                 // floats per stage (A+B)
#define GSMEM (2 * GSTGF * 4)              // 73728 bytes

__global__ __launch_bounds__(256, 2)
void gemm_mma(const float* __restrict__ A, const float* __restrict__ Bm,
              float* __restrict__ C, int M, int N, int K) {
    extern __shared__ float gsm[];
    const uint32_t sb = smem_u32(gsm);
    const int tid = threadIdx.x;
    const int lane = tid & 31, wid = tid >> 5;
    const int g = lane >> 2, c = lane & 3;
    const int bm = blockIdx.y * 128, bn = blockIdx.x * 128;
    const int wm = (wid >> 2) * 64, wn = (wid & 3) * 32;
    const int KIT = K >> 5;

    auto load_stage = [&](int s, int kt) {
        const uint32_t ab = sb + (uint32_t)s * (GSTGF * 4);
        const uint32_t bb = ab + 128 * GPAD * 4;
        const size_t kofs = (size_t)kt * 32;
#pragma unroll
        for (int i = 0; i < 4; i++) {
            int id = tid + i * 256;
            int row = id >> 3, c8 = id & 7;
            CP_ASYNC16(ab + (uint32_t)(row * (GPAD * 4) + c8 * 16),
                       A + (size_t)(bm + row) * K + kofs + c8 * 4);
        }
#pragma unroll
        for (int i = 0; i < 4; i++) {
            int id = tid + i * 256;
            int row = id >> 3, c8 = id & 7;
            CP_ASYNC16(bb + (uint32_t)(row * (GPAD * 4) + c8 * 16),
                       Bm + (size_t)(bn + row) * K + kofs + c8 * 4);
        }
    };

    float d[4][4][4];
#pragma unroll
    for (int mt = 0; mt < 4; mt++)
#pragma unroll
        for (int nt = 0; nt < 4; nt++)
#pragma unroll
            for (int i = 0; i < 4; i++) d[mt][nt][i] = 0.f;

    load_stage(0, 0);
    CP_COMMIT();

    for (int it = 0; it < KIT; it++) {
        if (it + 1 < KIT) load_stage((it + 1) & 1, it + 1);
        CP_COMMIT();
        CP_WAIT1();
        __syncthreads();

        const float* As = gsm + (it & 1) * GSTGF;
        const float* Bs = As + 128 * GPAD;
#pragma unroll
        for (int k0 = 0; k0 < 4; k0++) {
            uint32_t a[4][4];
#pragma unroll
            for (int mt = 0; mt < 4; mt++) {
                const float* p = As + (wm + mt * 16 + g) * GPAD + k0 * 8 + c;
                a[mt][0] = rtu(p[0]);
                a[mt][1] = rtu(p[8 * GPAD]);
                a[mt][2] = rtu(p[4]);
                a[mt][3] = rtu(p[8 * GPAD + 4]);
            }
            uint32_t b[4][2];
#pragma unroll
            for (int nt = 0; nt < 4; nt++) {
                const float* p = Bs + (wn + nt * 8 + g) * GPAD + k0 * 8 + c;
                b[nt][0] = rtu(p[0]);
                b[nt][1] = rtu(p[4]);
            }
#pragma unroll
            for (int mt = 0; mt < 4; mt++)
#pragma unroll
                for (int nt = 0; nt < 4; nt++)
                    mma_tf32(d[mt][nt], a[mt], b[nt]);
        }
        __syncthreads();
    }

#pragma unroll
    for (int mt = 0; mt < 4; mt++) {
        const int r0 = bm + wm + mt * 16 + g;
#pragma unroll
        for (int nt = 0; nt < 4; nt++) {
            const int c0 = bn + wn + nt * 8 + 2 * c;
            *(float2*)&C[(size_t)r0 * N + c0]       = make_float2(d[mt][nt][0], d[mt][nt][1]);
            *(float2*)&C[(size_t)(r0 + 8) * N + c0] = make_float2(d[mt][nt][2], d[mt][nt][3]);
        }
    }
}

// ---------------- q/k rmsnorm + RoPE (+ q * D^-0.5), in place on g_qkv ----------------
__global__ __launch_bounds__(256)
void prep_qk(float* __restrict__ qkv, const float* __restrict__ qw,
             const float* __restrict__ kw, const int* __restrict__ pos_ids) {
    const int bt = blockIdx.x;
    const int lane = threadIdx.x & 31;
    const int warp = threadIdx.x >> 5;
    const float pos = (float)pos_ids[bt];
    const float invf = expf(-(float)lane * (logf(10000.0f) / 32.0f));
    const float fr = pos * invf;
    const float cs = cosf(fr), sn = sinf(fr);

    for (int r = warp; r < 32; r += 8) {
        const int hh = r >> 1;
        const int isK = r & 1;
        float* row = qkv + (size_t)bt * QKVW + isK * (H_ * D_) + hh * D_;
        const float* w = isK ? kw : qw;
        float v0 = row[lane], v1 = row[lane + 32], v2 = row[lane + 64], v3 = row[lane + 96];
        float ss = v0 * v0 + v1 * v1 + v2 * v2 + v3 * v3;
#pragma unroll
        for (int o = 16; o; o >>= 1) ss += __shfl_xor_sync(0xFFFFFFFFu, ss, o);
        const float rs = rsqrtf(ss * (1.f / 128.f) + 1e-6f);
        v0 = v0 * rs * w[lane];      v1 = v1 * rs * w[lane + 32];
        v2 = v2 * rs * w[lane + 64]; v3 = v3 * rs * w[lane + 96];
        float nv0 = v0 * cs - v1 * sn;
        float nv1 = v1 * cs + v0 * sn;
        v0 = nv0; v1 = nv1;
        if (!isK) {
            const float sc = 0.08838834764831845f;
            v0 *= sc; v1 *= sc; v2 *= sc; v3 *= sc;
        }
        row[lane] = v0; row[lane + 32] = v1; row[lane + 64] = v2; row[lane + 96] = v3;
    }
}

// ================= chunked GLA with tf32 mma.sync tensor cores =================
// grid (4, H, B): block owns 32-wide dv slice; 64 sequential chunks.
// State S[128x32] lives in per-warp register fragments (fp32), mirrored to smem
// (tf32-rounded) once per chunk for the q@S mma B operand.
#define QS 132   // sQ/sK row stride (floats)
#define VS 36    // sV/sS row stride
#define AS 68    // sAtt row stride
#define GLA_SMEM_FLOATS (64*QS + 64*QS + 64*VS + 128*VS + 64*AS + 80)

__global__ __launch_bounds__(256, 1)
void gla_kernel(const float* __restrict__ qkv, float* __restrict__ o_out) {
    extern __shared__ float sm[];
    float* sQ   = sm;                  // [64][QS]
    float* sK   = sQ + 64 * QS;        // [64][QS]
    float* sV   = sK + 64 * QS;        // [64][VS]
    float* sS   = sV + 64 * VS;        // [128][VS]  (tf32-rounded copy of state)
    float* sAtt = sS + 128 * VS;       // [64][AS]
    float* expg = sAtt + 64 * AS;      // [80]

    const int tid = threadIdx.x;
    const int lane = tid & 31, w = tid >> 5;
    const int g = lane >> 2, c = lane & 3;
    const int gs = blockIdx.x;
    const int h  = blockIdx.y;
    const int b  = blockIdx.z;

    float gg;
    {
        const double scale = 1.0 - 11.0 / 31.0 + 1e-5;
        const double sl = pow(2.0, -0.5 * (double)(h + 1));
        gg = (float)(-sl * scale);
    }
    if (tid <= 64) expg[tid] = expf(gg * (float)tid);
    for (int i = tid; i < 128 * VS; i += 256) sS[i] = 0.f;

    // state fragments: warp w owns rows [16w,16w+16) x all 32 cols -> 4 n-tiles
    float fs[4][4];
#pragma unroll
    for (int nt = 0; nt < 4; nt++)
#pragma unroll
        for (int i = 0; i < 4; i++) fs[nt][i] = 0.f;

    __syncthreads();
    const float chdec = expg[64];

    const float* qb = qkv + (size_t)b * T_ * QKVW + h * D_;
    const int dvb = gs * 32;

    const int a_mq = (w >> 1) * 16;   // att phase m-tile
    const int a_ne = (w & 1) * 32;    // att phase 32-col half
    const int o_mo = (w >> 1) * 16;   // o phase m-tile
    const int o_no = (w & 1) * 16;    // o phase 16-col half
    const int s_m0 = w * 16;          // state phase m-tile

    for (int ck = 0; ck < NC_; ck++) {
        const float* crow = qb + (size_t)ck * CHK_ * QKVW;
        // ---- load q,k [64x128], v slice [64x32]; tf32-round on store ----
        for (int f = tid; f < 64 * 32; f += 256) {
            int r = f >> 5;
            int d4 = (f & 31) << 2;
            float4 qv = *(const float4*)(crow + (size_t)r * QKVW + d4);
            sQ[r * QS + d4 + 0] = rtf(qv.x); sQ[r * QS + d4 + 1] = rtf(qv.y);
            sQ[r * QS + d4 + 2] = rtf(qv.z); sQ[r * QS + d4 + 3] = rtf(qv.w);
            float4 kv = *(const float4*)(crow + (size_t)r * QKVW + 2048 + d4);
            sK[r * QS + d4 + 0] = rtf(kv.x); sK[r * QS + d4 + 1] = rtf(kv.y);
            sK[r * QS + d4 + 2] = rtf(kv.z); sK[r * QS + d4 + 3] = rtf(kv.w);
        }
        for (int f = tid; f < 64 * 8; f += 256) {
            int r = f >> 3;
            int d4 = (f & 7) << 2;
            float4 vv = *(const float4*)(crow + (size_t)r * QKVW + 4096 + dvb + d4);
            sV[r * VS + d4 + 0] = rtf(vv.x); sV[r * VS + d4 + 1] = rtf(vv.y);
            sV[r * VS + d4 + 2] = rtf(vv.z); sV[r * VS + d4 + 3] = rtf(vv.w);
        }
        __syncthreads();   // tiles + sS(prev chunk) visible

        // ---- att = Q @ K^T (64x64, k=128), mask+decay -> sAtt (rounded) ----
        {
            float fa[4][4];
#pragma unroll
            for (int nt = 0; nt < 4; nt++)
#pragma unroll
                for (int i = 0; i < 4; i++) fa[nt][i] = 0.f;
#pragma unroll
            for (int k0 = 0; k0 < 16; k0++) {
                uint32_t a[4];
                const float* pa = sQ + (a_mq + g) * QS + k0 * 8 + c;
                a[0] = __float_as_uint(pa[0]);
                a[1] = __float_as_uint(pa[8 * QS]);
                a[2] = __float_as_uint(pa[4]);
                a[3] = __float_as_uint(pa[8 * QS + 4]);
#pragma unroll
                for (int nt = 0; nt < 4; nt++) {
                    uint32_t bb[2];
                    const float* pb = sK + (a_ne + nt * 8 + g) * QS + k0 * 8 + c;
                    bb[0] = __float_as_uint(pb[0]);
                    bb[1] = __float_as_uint(pb[4]);
                    mma_tf32(fa[nt], a, bb);
                }
            }
#pragma unroll
            for (int nt = 0; nt < 4; nt++) {
                const int e0 = a_ne + nt * 8 + 2 * c;
                const int r0 = a_mq + g, r1 = a_mq + g + 8;
                float v;
                v = (r0 >= e0)     ? fa[nt][0] * expg[r0 - e0]     : 0.f;
                sAtt[r0 * AS + e0]     = rtf(v);
                v = (r0 >= e0 + 1) ? fa[nt][1] * expg[r0 - e0 - 1] : 0.f;
                sAtt[r0 * AS + e0 + 1] = rtf(v);
                v = (r1 >= e0)     ? fa[nt][2] * expg[r1 - e0]     : 0.f;
                sAtt[r1 * AS + e0]     = rtf(v);
                v = (r1 >= e0 + 1) ? fa[nt][3] * expg[r1 - e0 - 1] : 0.f;
                sAtt[r1 * AS + e0 + 1] = rtf(v);
            }
        }
        __syncthreads();

        // ---- o = att @ V + qdec * (Q @ S_prev)  (64x32) -> gmem ----
        {
            float fi[2][4], fr[2][4];
#pragma unroll
            for (int nt = 0; nt < 2; nt++)
#pragma unroll
                for (int i = 0; i < 4; i++) { fi[nt][i] = 0.f; fr[nt][i] = 0.f; }
#pragma unroll
            for (int k0 = 0; k0 < 8; k0++) {          // intra, k over e
                uint32_t a[4];
                const float* pa = sAtt + (o_mo + g) * AS + k0 * 8 + c;
                a[0] = __float_as_uint(pa[0]);
                a[1] = __float_as_uint(pa[8 * AS]);
                a[2] = __float_as_uint(pa[4]);
                a[3] = __float_as_uint(pa[8 * AS + 4]);
#pragma unroll
                for (int nt = 0; nt < 2; nt++) {
                    uint32_t bb[2];
                    bb[0] = __float_as_uint(sV[(k0 * 8 + c) * VS + o_no + nt * 8 + g]);
                    bb[1] = __float_as_uint(sV[(k0 * 8 + c + 4) * VS + o_no + nt * 8 + g]);
                    mma_tf32(fi[nt], a, bb);
                }
            }
#pragma unroll
            for (int k0 = 0; k0 < 16; k0++) {         // inter, k over d
                uint32_t a[4];
                const float* pa = sQ + (o_mo + g) * QS + k0 * 8 + c;
                a[0] = __float_as_uint(pa[0]);
                a[1] = __float_as_uint(pa[8 * QS]);
                a[2] = __float_as_uint(pa[4]);
                a[3] = __float_as_uint(pa[8 * QS + 4]);
#pragma unroll
                for (int nt = 0; nt < 2; nt++) {
                    uint32_t bb[2];
                    bb[0] = __float_as_uint(sS[(k0 * 8 + c) * VS + o_no + nt * 8 + g]);
                    bb[1] = __float_as_uint(sS[(k0 * 8 + c + 4) * VS + o_no + nt * 8 + g]);
                    mma_tf32(fr[nt], a, bb);
                }
            }
            const int r0 = o_mo + g, r1 = o_mo + g + 8;
            const float qd0 = expg[r0 + 1], qd1 = expg[r1 + 1];
            const size_t obase = ((size_t)b * T_ + (size_t)ck * CHK_) * HID_ + h * D_ + dvb;
#pragma unroll
            for (int nt = 0; nt < 2; nt++) {
                const int col = o_no + nt * 8 + 2 * c;
                *(float2*)(o_out + obase + (size_t)r0 * HID_ + col) =
                    make_float2(fi[nt][0] + qd0 * fr[nt][0], fi[nt][1] + qd0 * fr[nt][1]);
                *(float2*)(o_out + obase + (size_t)r1 * HID_ + col) =
                    make_float2(fi[nt][2] + qd1 * fr[nt][2], fi[nt][3] + qd1 * fr[nt][3]);
            }
        }

        // ---- state: fs = chdec*fs + (kdec*K)^T @ V   (128x32, k=64) ----
        {
#pragma unroll
            for (int nt = 0; nt < 4; nt++)
#pragma unroll
                for (int i = 0; i < 4; i++) fs[nt][i] *= chdec;
#pragma unroll
            for (int k0 = 0; k0 < 8; k0++) {
                const float kd0 = expg[63 - (k0 * 8 + c)];
                const float kd1 = expg[63 - (k0 * 8 + c + 4)];
                uint32_t a[4];
                a[0] = rtu(sK[(k0 * 8 + c) * QS + s_m0 + g] * kd0);
                a[1] = rtu(sK[(k0 * 8 + c) * QS + s_m0 + g + 8] * kd0);
                a[2] = rtu(sK[(k0 * 8 + c + 4) * QS + s_m0 + g] * kd1);
                a[3] = rtu(sK[(k0 * 8 + c + 4) * QS + s_m0 + g + 8] * kd1);
#pragma unroll
                for (int nt = 0; nt < 4; nt++) {
                    uint32_t bb[2];
                    bb[0] = __float_as_uint(sV[(k0 * 8 + c) * VS + nt * 8 + g]);
                    bb[1] = __float_as_uint(sV[(k0 * 8 + c + 4) * VS + nt * 8 + g]);
                    mma_tf32(fs[nt], a, bb);
                }
            }
        }
        __syncthreads();   // all reads of sS/sQ/sK/sV done

        // mirror state frags to sS (tf32-rounded) for next chunk's q@S
        {
            const int r0 = s_m0 + g, r1 = s_m0 + g + 8;
#pragma unroll
            for (int nt = 0; nt < 4; nt++) {
                const int col = nt * 8 + 2 * c;
                sS[r0 * VS + col]     = rtf(fs[nt][0]);
                sS[r0 * VS + col + 1] = rtf(fs[nt][1]);
                sS[r1 * VS + col]     = rtf(fs[nt][2]);
                sS[r1 * VS + col + 1] = rtf(fs[nt][3]);
            }
        }
        // next iteration's first __syncthreads() (after tile load) orders these
        // sS writes before the o-phase readers.
    }
}

// ---------------- group rmsnorm * sigmoid(gate) ----------------
__global__ __launch_bounds__(256)
void epilogue_k(const float* __restrict__ o_in, const float* __restrict__ gate,
                const float* __restrict__ gw, float* __restrict__ og) {
    const int bt = blockIdx.x;
    const int lane = threadIdx.x & 31;
    const int warp = threadIdx.x >> 5;
    for (int hh = warp; hh < H_; hh += 8) {
        const size_t base = (size_t)bt * HID_ + hh * D_;
        const float* row = o_in + base;
        float v0 = row[lane], v1 = row[lane + 32], v2 = row[lane + 64], v3 = row[lane + 96];
        float ss = v0 * v0 + v1 * v1 + v2 * v2 + v3 * v3;
#pragma unroll
        for (int o = 16; o; o >>= 1) ss += __shfl_xor_sync(0xFFFFFFFFu, ss, o);
        const float rs = rsqrtf(ss * (1.f / 128.f) + 1e-6f);
        const float* gr = gate + base;
        float* out = og + base;
#pragma unroll
        for (int i = 0; i < 4; i++) {
            const int d = lane + 32 * i;
            float v = (i == 0) ? v0 : (i == 1) ? v1 : (i == 2) ? v2 : v3;
            float sg = 1.f / (1.f + expf(-gr[d]));
            out[d] = v * rs * gw[hh * D_ + d] * sg;
        }
    }
}

// ---------------- launch ----------------
extern "C" void kernel_launch(void* const* d_in, const int* in_sizes, int n_in,
                              void* d_out, int out_size) {
    const float* hidden   = (const float*)d_in[0];
    const float* w_qkv    = (const float*)d_in[1];
    const float* q_ln_w   = (const float*)d_in[2];
    const float* k_ln_w   = (const float*)d_in[3];
    const float* g_norm_w = (const float*)d_in[4];
    const float* w_g_proj = (const float*)d_in[5];
    const float* w_dense  = (const float*)d_in[6];
    const int*   pos_ids  = (const int*)d_in[7];
    float* out = (float*)d_out;

    float *qkv_p, *gate_p, *o_p, *og_p;
    cudaGetSymbolAddress((void**)&qkv_p, g_qkv);
    cudaGetSymbolAddress((void**)&gate_p, g_gate);
    cudaGetSymbolAddress((void**)&o_p, g_o);
    cudaGetSymbolAddress((void**)&og_p, g_og);

    const int M = B_ * T_;
    cudaFuncSetAttribute(gla_kernel, cudaFuncAttributeMaxDynamicSharedMemorySize,
                         GLA_SMEM_FLOATS * (int)sizeof(float));
    cudaFuncSetAttribute(gemm_mma, cudaFuncAttributeMaxDynamicSharedMemorySize, GSMEM);

    // 1) qkv projection (tf32 mma.sync; RN rounding fused in fragment loads)
    gemm_mma<<<dim3(QKVW / 128, M / 128), 256, GSMEM>>>(hidden, w_qkv, qkv_p, M, QKVW, HID_);
    // 2) gate projection
    gemm_mma<<<dim3(HID_ / 128, M / 128), 256, GSMEM>>>(hidden, w_g_proj, gate_p, M, HID_, HID_);
    // 3) rmsnorm + rope on q,k
    prep_qk<<<M, 256>>>(qkv_p, q_ln_w, k_ln_w, pos_ids);
    // 4) chunked gated linear attention (tf32 tensor cores)
    gla_kernel<<<dim3(4, H_, B_), 256, GLA_SMEM_FLOATS * sizeof(float)>>>(qkv_p, o_p);
    // 5) group rmsnorm * sigmoid gate
    epilogue_k<<<M, 256>>>(o_p, gate_p, g_norm_w, og_p);
    // 6) dense output projection
    gemm_mma<<<dim3(HID_ / 128, M / 128), 256, GSMEM>>>(og_p, w_dense, out, M, HID_, HID_);
}